// round 15
// baseline (speedup 1.0000x reference)
#include <cuda_runtime.h>

#define BB     32
#define IDF    64
#define RES    128
#define QL     (RES*RES)      // 16384
#define CDF    768
#define SL     18
#define ADIM   100
#define NSPLIT 64
#define KCH    (QL/NSPLIT)    // 256
#define SP     9              // s-pairs

#define K2_STAGE_FLOATS (8*512)            // 8 channels x 512 q = 16KB
#define K2_SMEM_FLOATS  (3*K2_STAGE_FLOATS + IDF*20 + 32)
#define K2_SMEM_BYTES   (K2_SMEM_FLOATS*4)

// Scratch (no cudaMalloc allowed)
__device__ float g_sourceT2[2][BB*IDF*SL];    // [half][b][i][s] partials
__device__ float g_wctx2[BB*QL];              // [b][q]
__device__ float g_partial[NSPLIT*ADIM*BB];   // [split][a][b]

__device__ __forceinline__ unsigned long long pack2(float lo, float hi){
    unsigned long long r;
    asm("mov.b64 %0, {%1,%2};" : "=l"(r) : "f"(lo), "f"(hi));
    return r;
}
__device__ __forceinline__ void unpack2(unsigned long long v, float &lo, float &hi){
    asm("mov.b64 {%0,%1}, %2;" : "=f"(lo), "=f"(hi) : "l"(v));
}
// d = a*b + d  (packed 2x fp32, sm_100+ FFMA2)
__device__ __forceinline__ void ffma2(unsigned long long &d, unsigned long long a, unsigned long long b){
    asm("fma.rn.f32x2 %0, %1, %2, %0;" : "+l"(d) : "l"(a), "l"(b));
}
__device__ __forceinline__ void cp_async16(unsigned smem_addr, const void* gptr){
    asm volatile("cp.async.cg.shared.global [%0], [%1], 16;" :: "r"(smem_addr), "l"(gptr));
}

// ---------------------------------------------------------------------------
// k1: sourceT partials. This round: c-SPLIT for occupancy — grid
// (8 igroups, 32 b, 2 c-halves) = 512 blocks (was 256, 1.7 CTA/SM).
// Each block stages its 384-c half and computes a half-sum; k2 adds halves.
// Inner structure identical to the R3-proven version.
// ---------------------------------------------------------------------------
__global__ void __launch_bounds__(256) k1_sourceT(const float* __restrict__ ctx,
                                                  const float* __restrict__ w){
    const int b    = blockIdx.y;
    const int h    = blockIdx.z;                  // c-half
    const int tid  = threadIdx.x;
    const int lane = tid & 31;
    const int i    = blockIdx.x * 8 + (tid >> 5);
    const int c0   = h * 384;

    __shared__ float sctx[384*SL];     // 27 KB half of context[b]

    const float4* src = reinterpret_cast<const float4*>(ctx + (long long)b*CDF*SL + c0*SL);
    float4* dst = reinterpret_cast<float4*>(sctx);
    #pragma unroll
    for (int idx = tid; idx < 384*SL/4; idx += 256) dst[idx] = src[idx];
    __syncthreads();

    float acc[SL];
    #pragma unroll
    for (int s = 0; s < SL; ++s) acc[s] = 0.f;

    const float* wr = w + i*CDF + c0;
    #pragma unroll 4
    for (int j = 0; j < 12; ++j){
        const int c = lane + j*32;
        const float wv = __ldg(wr + c);
        const float* cp = &sctx[c*SL];
        #pragma unroll
        for (int s = 0; s < SL; ++s) acc[s] = fmaf(wv, cp[s], acc[s]);
    }

    #pragma unroll
    for (int off = 16; off; off >>= 1){
        #pragma unroll
        for (int s = 0; s < SL; ++s)
            acc[s] += __shfl_xor_sync(0xffffffffu, acc[s], off);
    }
    if (lane == 0){
        #pragma unroll
        for (int s = 0; s < SL; ++s)
            g_sourceT2[h][b*IDF*SL + i*SL + s] = acc[s];
    }
}

// ---------------------------------------------------------------------------
// k2: fused scores GEMV + softmax + cs-dot. R11-PROVEN 3-stage cp.async
// ring, 2 q/thread (34.9us measured). Only change: staging sums two
// sourceT halves.
// ---------------------------------------------------------------------------
__device__ __forceinline__ void k2_consume(const float2 xv, const float* rowf,
                                           unsigned long long* a0,
                                           unsigned long long* a1){
    unsigned long long t0 = pack2(xv.x, xv.x);
    unsigned long long t1 = pack2(xv.y, xv.y);
    const ulonglong2* r2 = reinterpret_cast<const ulonglong2*>(rowf);
    ulonglong2 v01 = r2[0];          // s0..s3
    ulonglong2 v23 = r2[1];          // s4..s7
    ulonglong2 v45 = r2[2];          // s8..s11
    ulonglong2 v67 = r2[3];          // s12..s15
    unsigned long long v8 = reinterpret_cast<const unsigned long long*>(rowf)[8]; // s16,s17
    ffma2(a0[0], t0, v01.x); ffma2(a1[0], t1, v01.x);
    ffma2(a0[1], t0, v01.y); ffma2(a1[1], t1, v01.y);
    ffma2(a0[2], t0, v23.x); ffma2(a1[2], t1, v23.x);
    ffma2(a0[3], t0, v23.y); ffma2(a1[3], t1, v23.y);
    ffma2(a0[4], t0, v45.x); ffma2(a1[4], t1, v45.x);
    ffma2(a0[5], t0, v45.y); ffma2(a1[5], t1, v45.y);
    ffma2(a0[6], t0, v67.x); ffma2(a1[6], t1, v67.x);
    ffma2(a0[7], t0, v67.y); ffma2(a1[7], t1, v67.y);
    ffma2(a0[8], t0, v8   ); ffma2(a1[8], t1, v8   );
}

__global__ void __launch_bounds__(256) k2_attn(const float* __restrict__ x,
                                               const float* __restrict__ conv_w,
                                               const float* __restrict__ conv_b){
    extern __shared__ __align__(16) float dsm[];
    float* sx   = dsm;                          // 3 stages x 4096 floats
    float* ssrc = dsm + 3*K2_STAGE_FLOATS;      // 64 rows, stride 20
    float* scs  = ssrc + IDF*20;                // 18 floats

    const int b   = blockIdx.y;
    const int tid = threadIdx.x;
    const int q0  = blockIdx.x * 512;
    const float* xbase = x + (long long)b*IDF*QL + q0;
    const unsigned sx_base = (unsigned)__cvta_generic_to_shared(sx);

    // per-thread copy slots: 4x 16B per stage (16KB / 256 threads)
    const int row0 = tid >> 7;            // 0..1
    const int off0 = (tid & 127) * 16;    // byte offset within 2KB row

    // prologue: start stages 0 and 1 immediately
    #pragma unroll
    for (int u = 0; u < 4; ++u){
        int ch = row0 + u*2;
        cp_async16(sx_base + ch*2048 + off0,
                   (const char*)(xbase + (long long)ch*QL) + off0);
    }
    asm volatile("cp.async.commit_group;");
    #pragma unroll
    for (int u = 0; u < 4; ++u){
        int ch = row0 + u*2;
        cp_async16(sx_base + 1*(K2_STAGE_FLOATS*4) + ch*2048 + off0,
                   (const char*)(xbase + (long long)(8 + ch)*QL) + off0);
    }
    asm volatile("cp.async.commit_group;");

    // stage sourceT rows (sum of halves) while prologue loads fly
    for (int idx = tid; idx < IDF*SL; idx += 256){
        int i = idx / SL, s = idx - i*SL;
        ssrc[i*20 + s] = g_sourceT2[0][b*IDF*SL + idx]
                       + g_sourceT2[1][b*IDF*SL + idx];
    }
    __syncthreads();
    if (tid < SL){
        float c = 0.f;
        #pragma unroll 8
        for (int i = 0; i < IDF; ++i)
            c = fmaf(__ldg(conv_w + i), ssrc[i*20 + tid], c);
        scs[tid] = c;          // consumed in epilogue; chunk-loop syncs cover it
    }

    unsigned long long a0[SP], a1[SP];
    #pragma unroll
    for (int p = 0; p < SP; ++p){ a0[p]=0ULL; a1[p]=0ULL; }

    #pragma unroll 1
    for (int c = 0; c < 8; ++c){
        if (c == 7) asm volatile("cp.async.wait_group 0;");
        else        asm volatile("cp.async.wait_group 1;");   // stages <= c done
        __syncthreads();            // cross-thread visibility + slot reuse safety
        if (c < 6){                 // issue stage c+2 into slot (c+2)%3
            const int nslot = (c+2) % 3;
            const float* xc = xbase + (long long)(c+2)*8*QL;
            #pragma unroll
            for (int u = 0; u < 4; ++u){
                int ch = row0 + u*2;
                cp_async16(sx_base + nslot*(K2_STAGE_FLOATS*4) + ch*2048 + off0,
                           (const char*)(xc + (long long)ch*QL) + off0);
            }
            asm volatile("cp.async.commit_group;");
        }
        const float* rowc = ssrc + c*(8*20);
        const float* sxc  = sx + (c % 3)*K2_STAGE_FLOATS + tid*2;
        #pragma unroll
        for (int j = 0; j < 8; ++j){
            float2 xv = *reinterpret_cast<const float2*>(sxc + j*512);
            k2_consume(xv, rowc + j*20, a0, a1);
        }
    }

    // epilogue: softmax (max-free: |score| << 88) + cs dot
    float sa[SL], sb[SL];
    #pragma unroll
    for (int p = 0; p < SP; ++p){
        unpack2(a0[p], sa[2*p], sa[2*p+1]);
        unpack2(a1[p], sb[2*p], sb[2*p+1]);
    }
    float d0 = 0.f, d1 = 0.f, n0 = 0.f, n1 = 0.f;
    #pragma unroll
    for (int s = 0; s < SL; ++s){
        float e0 = __expf(sa[s]);
        float e1 = __expf(sb[s]);
        float cc = scs[s];
        d0 += e0; d1 += e1;
        n0 = fmaf(e0, cc, n0);
        n1 = fmaf(e1, cc, n1);
    }
    const float cb = conv_b[0];
    float2 o2 = make_float2(n0/d0 + cb, n1/d1 + cb);
    *reinterpret_cast<float2*>(&g_wctx2[b*QL + q0 + tid*2]) = o2;
}

// ---------------------------------------------------------------------------
// k3: split-K FC partials (R3-proven, separate launch).
// ---------------------------------------------------------------------------
__global__ void __launch_bounds__(256) k3_fc(const float* __restrict__ fcw){
    const int split = blockIdx.x;
    const int k0    = split * KCH;
    const int tid   = threadIdx.x;
    const int lane  = tid & 31;
    const int w     = tid >> 5;

    __shared__ float sm[KCH*33];   // [k][b], padded (33.8 KB)
    for (int idx = tid; idx < BB*KCH; idx += 256){
        int b = idx >> 8;          // /256
        int k = idx & 255;
        sm[k*33 + b] = g_wctx2[b*QL + k0 + k];
    }
    __syncthreads();

    const int a0 = blockIdx.y * 16 + w * 2;   // a-pair {a0, a0+1}
    if (a0 >= ADIM) return;

    const float4* f0 = reinterpret_cast<const float4*>(fcw + (long long)(a0  )*QL + k0);
    const float4* f1 = reinterpret_cast<const float4*>(fcw + (long long)(a0+1)*QL + k0);
    float acc0 = 0.f, acc1 = 0.f;
    #pragma unroll 8
    for (int kq = 0; kq < KCH/4; ++kq){
        float4 x0 = __ldg(f0 + kq);
        float4 x1 = __ldg(f1 + kq);
        const int k = kq*4;
        float v0 = sm[(k+0)*33 + lane];
        float v1 = sm[(k+1)*33 + lane];
        float v2 = sm[(k+2)*33 + lane];
        float v3 = sm[(k+3)*33 + lane];
        acc0 = fmaf(x0.x, v0, acc0);  acc1 = fmaf(x1.x, v0, acc1);
        acc0 = fmaf(x0.y, v1, acc0);  acc1 = fmaf(x1.y, v1, acc1);
        acc0 = fmaf(x0.z, v2, acc0);  acc1 = fmaf(x1.z, v2, acc1);
        acc0 = fmaf(x0.w, v3, acc0);  acc1 = fmaf(x1.w, v3, acc1);
    }
    g_partial[split*(ADIM*BB) + (a0  )*BB + lane] = acc0;
    g_partial[split*(ADIM*BB) + (a0+1)*BB + lane] = acc1;
}

// ---------------------------------------------------------------------------
// k4: parallel reduce of split partials (R3-proven, separate launch).
// ---------------------------------------------------------------------------
__global__ void __launch_bounds__(256) k4_reduce(const float* __restrict__ fcb,
                                                 float* __restrict__ out){
    const int a   = blockIdx.x;          // 0..99
    const int tid = threadIdx.x;
    const int b   = tid & 31;
    const int g   = tid >> 5;            // 0..7

    float acc = 0.f;
    #pragma unroll
    for (int sp = g; sp < NSPLIT; sp += 8)
        acc += g_partial[sp*(ADIM*BB) + a*BB + b];

    __shared__ float red[256];
    red[tid] = acc;
    __syncthreads();
    if (g == 0){
        float v = red[b] + red[b+32] + red[b+64] + red[b+96]
                + red[b+128] + red[b+160] + red[b+192] + red[b+224];
        out[b*ADIM + a] = v + fcb[a];
    }
}

extern "C" void kernel_launch(void* const* d_in, const int* in_sizes, int n_in,
                              void* d_out, int out_size){
    const float* inputs     = (const float*)d_in[0];  // [32,64,128,128]
    const float* context    = (const float*)d_in[1];  // [32,768,18]
    const float* conv_ctx_w = (const float*)d_in[2];  // [64,768]
    const float* conv_w     = (const float*)d_in[3];  // [64]
    const float* conv_b     = (const float*)d_in[4];  // [1]
    const float* fc_w       = (const float*)d_in[5];  // [100,16384]
    const float* fc_b       = (const float*)d_in[6];  // [100]
    float* out = (float*)d_out;                        // [32,100]

    cudaFuncSetAttribute(k2_attn, cudaFuncAttributeMaxDynamicSharedMemorySize,
                         K2_SMEM_BYTES);

    k1_sourceT<<<dim3(8, BB, 2), 256>>>(context, conv_ctx_w);
    k2_attn   <<<dim3(QL/512, BB), 256, K2_SMEM_BYTES>>>(inputs, conv_w, conv_b);
    k3_fc     <<<dim3(NSPLIT, 7), 256>>>(fc_w);
    k4_reduce <<<ADIM, 256>>>(fc_b, out);
}

// round 16
// speedup vs baseline: 1.0045x; 1.0045x over previous
#include <cuda_runtime.h>

#define BB     32
#define IDF    64
#define RES    128
#define QL     (RES*RES)      // 16384
#define CDF    768
#define SL     18
#define ADIM   100
#define NSPLIT 64
#define KCH    (QL/NSPLIT)    // 256
#define SP     9              // s-pairs

#define K2_STAGE_FLOATS (8*512)            // 8 channels x 512 q = 16KB
#define K2_SMEM_FLOATS  (3*K2_STAGE_FLOATS + IDF*20 + 32)
#define K2_SMEM_BYTES   (K2_SMEM_FLOATS*4)

// Scratch (no cudaMalloc allowed)
__device__ float g_sourceT[BB*IDF*SL];        // [b][i][s]
__device__ float g_wctx2[BB*QL];              // [b][q]
__device__ float g_partial[NSPLIT*ADIM*BB];   // [split][a][b]

__device__ __forceinline__ unsigned long long pack2(float lo, float hi){
    unsigned long long r;
    asm("mov.b64 %0, {%1,%2};" : "=l"(r) : "f"(lo), "f"(hi));
    return r;
}
__device__ __forceinline__ void unpack2(unsigned long long v, float &lo, float &hi){
    asm("mov.b64 {%0,%1}, %2;" : "=f"(lo), "=f"(hi) : "l"(v));
}
// d = a*b + d  (packed 2x fp32, sm_100+ FFMA2)
__device__ __forceinline__ void ffma2(unsigned long long &d, unsigned long long a, unsigned long long b){
    asm("fma.rn.f32x2 %0, %1, %2, %0;" : "+l"(d) : "l"(a), "l"(b));
}
__device__ __forceinline__ void cp_async8(unsigned smem_addr, const void* gptr){
    asm volatile("cp.async.ca.shared.global [%0], [%1], 8;" :: "r"(smem_addr), "l"(gptr));
}

// ---------------------------------------------------------------------------
// k1: sourceT[b,i,s] = sum_c conv_ctx_w[i,c] * context[b,c,s]
// R3-PROVEN VERSION (10.8us measured). Frozen permanently.
// ---------------------------------------------------------------------------
__global__ void __launch_bounds__(256) k1_sourceT(const float* __restrict__ ctx,
                                                  const float* __restrict__ w){
    const int b    = blockIdx.y;
    const int tid  = threadIdx.x;
    const int lane = tid & 31;
    const int i    = blockIdx.x * 8 + (tid >> 5);

    __shared__ float sctx[384*SL];     // 27 KB chunk of context[b]

    float acc[SL];
    #pragma unroll
    for (int s = 0; s < SL; ++s) acc[s] = 0.f;

    for (int c0 = 0; c0 < CDF; c0 += 384){
        __syncthreads();
        const float4* src = reinterpret_cast<const float4*>(ctx + (long long)b*CDF*SL + c0*SL);
        float4* dst = reinterpret_cast<float4*>(sctx);
        #pragma unroll
        for (int idx = tid; idx < 384*SL/4; idx += 256) dst[idx] = src[idx];
        __syncthreads();

        const float* wr = w + i*CDF + c0;
        #pragma unroll 4
        for (int j = 0; j < 12; ++j){
            const int c = lane + j*32;
            const float wv = __ldg(wr + c);
            const float* cp = &sctx[c*SL];
            #pragma unroll
            for (int s = 0; s < SL; ++s) acc[s] = fmaf(wv, cp[s], acc[s]);
        }
    }

    #pragma unroll
    for (int off = 16; off; off >>= 1){
        #pragma unroll
        for (int s = 0; s < SL; ++s)
            acc[s] += __shfl_xor_sync(0xffffffffu, acc[s], off);
    }
    if (lane == 0){
        #pragma unroll
        for (int s = 0; s < SL; ++s)
            g_sourceT[b*IDF*SL + i*SL + s] = acc[s];
    }
}

// ---------------------------------------------------------------------------
// k2: fused scores GEMV + softmax + cs-dot. This round: THREAD-PRIVATE
// 3-stage cp.async pipeline — each thread copies exactly the 8B/channel it
// consumes (cp.async.ca 8B), so wait_group (per-thread) is the only
// synchronization and ALL mainloop __syncthreads are deleted. Warps
// free-run. 2 q/thread, grid (32 qtiles, 32 b).
// ---------------------------------------------------------------------------
__device__ __forceinline__ void k2_consume(const float2 xv, const float* rowf,
                                           unsigned long long* a0,
                                           unsigned long long* a1){
    unsigned long long t0 = pack2(xv.x, xv.x);
    unsigned long long t1 = pack2(xv.y, xv.y);
    const ulonglong2* r2 = reinterpret_cast<const ulonglong2*>(rowf);
    ulonglong2 v01 = r2[0];          // s0..s3
    ulonglong2 v23 = r2[1];          // s4..s7
    ulonglong2 v45 = r2[2];          // s8..s11
    ulonglong2 v67 = r2[3];          // s12..s15
    unsigned long long v8 = reinterpret_cast<const unsigned long long*>(rowf)[8]; // s16,s17
    ffma2(a0[0], t0, v01.x); ffma2(a1[0], t1, v01.x);
    ffma2(a0[1], t0, v01.y); ffma2(a1[1], t1, v01.y);
    ffma2(a0[2], t0, v23.x); ffma2(a1[2], t1, v23.x);
    ffma2(a0[3], t0, v23.y); ffma2(a1[3], t1, v23.y);
    ffma2(a0[4], t0, v45.x); ffma2(a1[4], t1, v45.x);
    ffma2(a0[5], t0, v45.y); ffma2(a1[5], t1, v45.y);
    ffma2(a0[6], t0, v67.x); ffma2(a1[6], t1, v67.x);
    ffma2(a0[7], t0, v67.y); ffma2(a1[7], t1, v67.y);
    ffma2(a0[8], t0, v8   ); ffma2(a1[8], t1, v8   );
}

__global__ void __launch_bounds__(256) k2_attn(const float* __restrict__ x,
                                               const float* __restrict__ conv_w,
                                               const float* __restrict__ conv_b){
    extern __shared__ __align__(16) float dsm[];
    float* sx   = dsm;                          // 3 stages x 4096 floats
    float* ssrc = dsm + 3*K2_STAGE_FLOATS;      // 64 rows, stride 20
    float* scs  = ssrc + IDF*20;                // 18 floats

    const int b   = blockIdx.y;
    const int tid = threadIdx.x;
    const int q0  = blockIdx.x * 512;
    const float* xbase = x + (long long)b*IDF*QL + q0;
    const unsigned sx_base = (unsigned)__cvta_generic_to_shared(sx);
    const int toff = tid * 8;                   // this thread's 8B slot per 2KB row

    // prologue: issue stages 0 and 1 — this thread's own bytes only
    #pragma unroll
    for (int ch = 0; ch < 8; ++ch)
        cp_async8(sx_base + ch*2048 + toff,
                  (const char*)(xbase + (long long)ch*QL) + toff);
    asm volatile("cp.async.commit_group;");
    #pragma unroll
    for (int ch = 0; ch < 8; ++ch)
        cp_async8(sx_base + 1*(K2_STAGE_FLOATS*4) + ch*2048 + toff,
                  (const char*)(xbase + (long long)(8 + ch)*QL) + toff);
    asm volatile("cp.async.commit_group;");

    // stage sourceT rows (cross-thread; one barrier) + cs
    for (int idx = tid; idx < IDF*SL; idx += 256){
        int i = idx / SL, s = idx - i*SL;
        ssrc[i*20 + s] = g_sourceT[b*IDF*SL + idx];
    }
    __syncthreads();
    if (tid < SL){
        float c = 0.f;
        #pragma unroll 8
        for (int i = 0; i < IDF; ++i)
            c = fmaf(__ldg(conv_w + i), ssrc[i*20 + tid], c);
        scs[tid] = c;          // visibility via the post-loop barrier
    }

    unsigned long long a0[SP], a1[SP];
    #pragma unroll
    for (int p = 0; p < SP; ++p){ a0[p]=0ULL; a1[p]=0ULL; }

    // BARRIER-FREE mainloop: per-thread wait_group; slots are thread-private
    #pragma unroll 1
    for (int c = 0; c < 8; ++c){
        if (c == 7) asm volatile("cp.async.wait_group 0;" ::: "memory");
        else        asm volatile("cp.async.wait_group 1;" ::: "memory");
        if (c < 6){                 // issue stage c+2 into slot (c+2)%3
            const int nslot = (c+2) % 3;
            const float* xc = xbase + (long long)(c+2)*8*QL;
            #pragma unroll
            for (int ch = 0; ch < 8; ++ch)
                cp_async8(sx_base + nslot*(K2_STAGE_FLOATS*4) + ch*2048 + toff,
                          (const char*)(xc + (long long)ch*QL) + toff);
            asm volatile("cp.async.commit_group;");
        }
        const float* rowc = ssrc + c*(8*20);
        const float* sxc  = sx + (c % 3)*K2_STAGE_FLOATS + tid*2;
        #pragma unroll
        for (int j = 0; j < 8; ++j){
            float2 xv = *reinterpret_cast<const float2*>(sxc + j*512);
            k2_consume(xv, rowc + j*20, a0, a1);
        }
    }
    __syncthreads();   // scs visibility for epilogue

    // epilogue: softmax (max-free: |score| << 88) + cs dot
    float sa[SL], sb[SL];
    #pragma unroll
    for (int p = 0; p < SP; ++p){
        unpack2(a0[p], sa[2*p], sa[2*p+1]);
        unpack2(a1[p], sb[2*p], sb[2*p+1]);
    }
    float d0 = 0.f, d1 = 0.f, n0 = 0.f, n1 = 0.f;
    #pragma unroll
    for (int s = 0; s < SL; ++s){
        float e0 = __expf(sa[s]);
        float e1 = __expf(sb[s]);
        float cc = scs[s];
        d0 += e0; d1 += e1;
        n0 = fmaf(e0, cc, n0);
        n1 = fmaf(e1, cc, n1);
    }
    const float cb = conv_b[0];
    float2 o2 = make_float2(n0/d0 + cb, n1/d1 + cb);
    *reinterpret_cast<float2*>(&g_wctx2[b*QL + q0 + tid*2]) = o2;
}

// ---------------------------------------------------------------------------
// k3: split-K FC partials (R3-proven, separate launch).
// ---------------------------------------------------------------------------
__global__ void __launch_bounds__(256) k3_fc(const float* __restrict__ fcw){
    const int split = blockIdx.x;
    const int k0    = split * KCH;
    const int tid   = threadIdx.x;
    const int lane  = tid & 31;
    const int w     = tid >> 5;

    __shared__ float sm[KCH*33];   // [k][b], padded (33.8 KB)
    for (int idx = tid; idx < BB*KCH; idx += 256){
        int b = idx >> 8;          // /256
        int k = idx & 255;
        sm[k*33 + b] = g_wctx2[b*QL + k0 + k];
    }
    __syncthreads();

    const int a0 = blockIdx.y * 16 + w * 2;   // a-pair {a0, a0+1}
    if (a0 >= ADIM) return;

    const float4* f0 = reinterpret_cast<const float4*>(fcw + (long long)(a0  )*QL + k0);
    const float4* f1 = reinterpret_cast<const float4*>(fcw + (long long)(a0+1)*QL + k0);
    float acc0 = 0.f, acc1 = 0.f;
    #pragma unroll 8
    for (int kq = 0; kq < KCH/4; ++kq){
        float4 x0 = __ldg(f0 + kq);
        float4 x1 = __ldg(f1 + kq);
        const int k = kq*4;
        float v0 = sm[(k+0)*33 + lane];
        float v1 = sm[(k+1)*33 + lane];
        float v2 = sm[(k+2)*33 + lane];
        float v3 = sm[(k+3)*33 + lane];
        acc0 = fmaf(x0.x, v0, acc0);  acc1 = fmaf(x1.x, v0, acc1);
        acc0 = fmaf(x0.y, v1, acc0);  acc1 = fmaf(x1.y, v1, acc1);
        acc0 = fmaf(x0.z, v2, acc0);  acc1 = fmaf(x1.z, v2, acc1);
        acc0 = fmaf(x0.w, v3, acc0);  acc1 = fmaf(x1.w, v3, acc1);
    }
    g_partial[split*(ADIM*BB) + (a0  )*BB + lane] = acc0;
    g_partial[split*(ADIM*BB) + (a0+1)*BB + lane] = acc1;
}

// ---------------------------------------------------------------------------
// k4: parallel reduce of split partials (R3-proven, separate launch).
// ---------------------------------------------------------------------------
__global__ void __launch_bounds__(256) k4_reduce(const float* __restrict__ fcb,
                                                 float* __restrict__ out){
    const int a   = blockIdx.x;          // 0..99
    const int tid = threadIdx.x;
    const int b   = tid & 31;
    const int g   = tid >> 5;            // 0..7

    float acc = 0.f;
    #pragma unroll
    for (int sp = g; sp < NSPLIT; sp += 8)
        acc += g_partial[sp*(ADIM*BB) + a*BB + b];

    __shared__ float red[256];
    red[tid] = acc;
    __syncthreads();
    if (g == 0){
        float v = red[b] + red[b+32] + red[b+64] + red[b+96]
                + red[b+128] + red[b+160] + red[b+192] + red[b+224];
        out[b*ADIM + a] = v + fcb[a];
    }
}

extern "C" void kernel_launch(void* const* d_in, const int* in_sizes, int n_in,
                              void* d_out, int out_size){
    const float* inputs     = (const float*)d_in[0];  // [32,64,128,128]
    const float* context    = (const float*)d_in[1];  // [32,768,18]
    const float* conv_ctx_w = (const float*)d_in[2];  // [64,768]
    const float* conv_w     = (const float*)d_in[3];  // [64]
    const float* conv_b     = (const float*)d_in[4];  // [1]
    const float* fc_w       = (const float*)d_in[5];  // [100,16384]
    const float* fc_b       = (const float*)d_in[6];  // [100]
    float* out = (float*)d_out;                        // [32,100]

    cudaFuncSetAttribute(k2_attn, cudaFuncAttributeMaxDynamicSharedMemorySize,
                         K2_SMEM_BYTES);

    k1_sourceT<<<dim3(8, BB), 256>>>(context, conv_ctx_w);
    k2_attn   <<<dim3(QL/512, BB), 256, K2_SMEM_BYTES>>>(inputs, conv_w, conv_b);
    k3_fc     <<<dim3(NSPLIT, 7), 256>>>(fc_w);
    k4_reduce <<<ADIM, 256>>>(fc_b, out);
}